// round 13
// baseline (speedup 1.0000x reference)
#include <cuda_runtime.h>

#define MAXROWS (1 << 22)
#define MAXB 2048
#define MAXM 32
#define NTILE 8
#define MAXDW 512     // force-bitmap words; supports D <= 16384
#define MAXCHUNK 16

#define K1_TPB 256
#define K1_ITER 4
#define K1_CHUNK (K1_TPB * K1_ITER)   // 1024 priors per CTA

__device__ short g_objth[MAXROWS];                    // -1 = below threshold, else obj idx
__device__ uint4 g_cand[MAXB * MAXM * MAXCHUNK];      // (inter,den,d) per (b,m,chunk)
__device__ float g_ce[MAXROWS];
__device__ float g_partc[MAXB * NTILE];
__device__ float g_partl[MAXB * NTILE];
__device__ int   g_parti[MAXB * NTILE];
__device__ float g_loss[MAXB];
__device__ int   g_npos[MAXB];
__device__ int   g_count;                             // zero-init; self-reset

__device__ __forceinline__ float warpReduceSumF(float v) {
#pragma unroll
    for (int o = 16; o; o >>= 1) v += __shfl_down_sync(0xffffffffu, v, o);
    return v;
}
__device__ __forceinline__ int warpReduceSumI(int v) {
#pragma unroll
    for (int o = 16; o; o >>= 1) v += __shfl_down_sync(0xffffffffu, v, o);
    return v;
}
__device__ __forceinline__ float blockReduceSumF(float v, float* sh) {
    int lane = threadIdx.x & 31, wid = threadIdx.x >> 5;
    int nw = (blockDim.x + 31) >> 5;
    v = warpReduceSumF(v);
    if (lane == 0) sh[wid] = v;
    __syncthreads();
    float r = 0.f;
    if (wid == 0) {
        r = (lane < nw) ? sh[lane] : 0.f;
        r = warpReduceSumF(r);
        if (lane == 0) sh[0] = r;
    }
    __syncthreads();
    r = sh[0];
    __syncthreads();
    return r;
}
__device__ __forceinline__ int blockReduceSumI(int v, int* sh) {
    int lane = threadIdx.x & 31, wid = threadIdx.x >> 5;
    int nw = (blockDim.x + 31) >> 5;
    v = warpReduceSumI(v);
    if (lane == 0) sh[wid] = v;
    __syncthreads();
    int r = 0;
    if (wid == 0) {
        r = (lane < nw) ? sh[lane] : 0;
        r = warpReduceSumI(r);
        if (lane == 0) sh[0] = r;
    }
    __syncthreads();
    r = sh[0];
    __syncthreads();
    return r;
}

// ==== K1: IoUs once, ITER=4 priors/thread. Reference-bit-identical (inter,den)
// keys; exact rational compares. Warp shuffle -> CTA reduce -> uint4/chunk.
// grid (ceil(D/1024), B), 256 threads, ~4KB static smem -> high occupancy.
__global__ void __launch_bounds__(K1_TPB, 4)
mb_match_kernel(const float* __restrict__ gt_boxes,
                const float* __restrict__ dbox,
                int D, int M)
{
    __shared__ float4 s_g[MAXM];        // gt xyxy (reference layout)
    __shared__ float  s_a[MAXM];        // gt area
    __shared__ float  s_wi[MAXM * 8];   // per-warp winner inter
    __shared__ float  s_wn[MAXM * 8];   // per-warp winner den
    __shared__ int    s_wd[MAXM * 8];   // per-warp winner d

    const int b = blockIdx.y;
    const int tid = threadIdx.x;
    const int lane = tid & 31, w = tid >> 5;
    const float4* db4 = (const float4*)dbox;

    if (tid < M) {
        float4 g = ((const float4*)gt_boxes)[(size_t)b * M + tid];  // xyxy
        s_g[tid] = g;
        s_a[tid] = (g.z - g.x) * (g.w - g.y);
    }
    __syncthreads();

    int   dd[K1_ITER];
    float px1[K1_ITER], py1[K1_ITER], px2[K1_ITER], py2[K1_ITER], pa[K1_ITER];
#pragma unroll
    for (int i = 0; i < K1_ITER; i++) {
        int d = blockIdx.x * K1_CHUNK + i * K1_TPB + tid;
        dd[i] = d;
        int dl = min(d, D - 1);         // phantoms mirror D-1: exact tie -> lose min-d
        float4 p = db4[dl];             // cxcywh
        // reference: c - wh/2, c + wh/2  ( /2 == *0.5f exactly )
        px1[i] = p.x - p.z * 0.5f; py1[i] = p.y - p.w * 0.5f;
        px2[i] = p.x + p.z * 0.5f; py2[i] = p.y + p.w * 0.5f;
        pa[i]  = (px2[i] - px1[i]) * (py2[i] - py1[i]);   // reference area_b
    }

    float binter[K1_ITER], bden[K1_ITER];
    int   bi[K1_ITER];
#pragma unroll
    for (int i = 0; i < K1_ITER; i++) { binter[i] = -1.f; bden[i] = 1.f; bi[i] = 0; }

    for (int m = 0; m < M; m++) {
        float4 g = s_g[m];
        float ga = s_a[m];
        float minter = -1.f, mden = 1.f;
        int   md = dd[0];
#pragma unroll
        for (int i = 0; i < K1_ITER; i++) {
            // reference intersection (xyxy min/max, clip 0)
            float ww = fmaxf(fminf(g.z, px2[i]) - fmaxf(g.x, px1[i]), 0.f);
            float hh = fmaxf(fminf(g.w, py2[i]) - fmaxf(g.y, py1[i]), 0.f);
            float inter = ww * hh;
            float den = (ga + pa[i]) - inter;             // reference union
            // iou_a > iou_b  <=>  i_a*d_b > i_b*d_a   (exact rational)
            if (inter * bden[i] > binter[i] * den) { binter[i] = inter; bden[i] = den; bi[i] = m; }
            if (inter * mden > minter * den)       { minter = inter; mden = den; md = dd[i]; }
        }
        // warp reduce per-m winner (max iou, tie -> min d)
#pragma unroll
        for (int o = 16; o; o >>= 1) {
            float oi = __shfl_down_sync(0xffffffffu, minter, o);
            float on = __shfl_down_sync(0xffffffffu, mden, o);
            int   od = __shfl_down_sync(0xffffffffu, md, o);
            float c1 = oi * mden, c2 = minter * on;
            if (c1 > c2 || (c1 == c2 && od < md)) { minter = oi; mden = on; md = od; }
        }
        if (lane == 0) {
            s_wi[m * 8 + w] = minter;
            s_wn[m * 8 + w] = mden;
            s_wd[m * 8 + w] = md;
        }
    }

    // per-d labels: iou < 0.5  <=>  2*inter < den  (R11 exact form)
#pragma unroll
    for (int i = 0; i < K1_ITER; i++)
        if (dd[i] < D)
            g_objth[(size_t)b * D + dd[i]] =
                (2.f * binter[i] < bden[i]) ? (short)-1 : (short)bi[i];
    __syncthreads();

    // CTA reduce over 8 warps, emit chunk candidate
    if (tid < M) {
        float fi = -1.f, fn = 1.f;
        int   fd = 0x7FFFFFFF;
#pragma unroll
        for (int j = 0; j < 8; j++) {
            float ci = s_wi[tid * 8 + j], cn = s_wn[tid * 8 + j];
            int   cd = s_wd[tid * 8 + j];
            float c1 = ci * fn, c2 = fi * cn;
            if (c1 > c2 || (c1 == c2 && cd < fd)) { fi = ci; fn = cn; fd = cd; }
        }
        uint4 outc;
        outc.x = __float_as_uint(fi);
        outc.y = __float_as_uint(fn);
        outc.z = (unsigned)fd;
        outc.w = 0u;
        g_cand[((size_t)b * MAXM + tid) * MAXCHUNK + blockIdx.x] = outc;
    }
}

// ==== K2: CE + labels + loc, high occupancy. grid (NTILE, B), 256 threads ===
// dyn smem: 256*C floats staging.
__global__ void __launch_bounds__(256)
mb_ce_kernel(const float* __restrict__ cls_pred,
             const float* __restrict__ loc_pred,
             const float* __restrict__ gt_boxes,
             const int*   __restrict__ gt_labels,
             const float* __restrict__ dbox,
             int D, int M, int C, int nchunk)
{
    extern __shared__ float s_stage[];               // [8 warps][32*C]
    __shared__ float4 s_g[MAXM];
    __shared__ int    s_glab[MAXM];
    __shared__ int    s_dpg[MAXM];
    __shared__ unsigned s_fbit[MAXDW];
    __shared__ float  s_redf[32];
    __shared__ int    s_redi[32];

    const int b = blockIdx.y, t = blockIdx.x;
    const int tid = threadIdx.x;
    const int lane = tid & 31, w = tid >> 5;
    const int warps_per_batch = gridDim.x * 8;
    const int nwords = (D + 31) >> 5;
    const float4* db4 = (const float4*)dbox;

    for (int i = tid; i < nwords; i += 256) s_fbit[i] = 0u;
    if (tid < MAXM) s_dpg[tid] = -2;
    __syncthreads();
    if (tid < M) {
        float4 g = ((const float4*)gt_boxes)[(size_t)b * M + tid];
        s_g[tid] = g;
        s_glab[tid] = gt_labels[(size_t)b * M + tid];
        // exact reduce of per-chunk candidates (fixed order, deterministic)
        float fi = -1.f, fn = 1.f;
        int   fd = 0x7FFFFFFF;
        for (int c = 0; c < nchunk; c++) {
            uint4 cd4 = g_cand[((size_t)b * MAXM + tid) * MAXCHUNK + c];
            float ci = __uint_as_float(cd4.x), cn = __uint_as_float(cd4.y);
            int   cd = (int)cd4.z;
            float c1 = ci * fn, c2 = fi * cn;
            if (c1 > c2 || (c1 == c2 && cd < fd)) { fi = ci; fn = cn; fd = cd; }
        }
        s_dpg[tid] = fd;
        atomicOr(&s_fbit[fd >> 5], 1u << (fd & 31));
    }
    __syncthreads();

    float conf = 0.f, locs = 0.f;
    int npos = 0;
    int ntiles = (D + 31) >> 5;
    float* sw = s_stage + (size_t)w * 32 * C;

    for (int tt = t * 8 + w; tt < ntiles; tt += warps_per_batch) {
        int r0 = tt * 32;
        int nr = min(32, D - r0);
        const float* src = cls_pred + ((size_t)b * D + r0) * C;
        if (nr == 32) {
            const float4* s4 = (const float4*)src;
            int nf4 = 8 * C;
            for (int i = lane; i < nf4; i += 32)
                ((float4*)sw)[i] = s4[i];
        } else {
            int nf = nr * C;
            for (int i = lane; i < nf; i += 32)
                sw[i] = src[i];
        }
        __syncwarp();
        if (lane < nr) {
            int r = r0 + lane;
            size_t row = (size_t)b * D + r;
            // forced? (rare: bitmap test first, then last-write-wins scan)
            int mf = -1;
            if ((s_fbit[r >> 5] >> (r & 31)) & 1u) {
#pragma unroll
                for (int j = 0; j < MAXM; j++)
                    if (s_dpg[j] == r) mf = j;        // later j wins
            }
            int m, lab;
            if (mf >= 0) { m = mf; lab = s_glab[m]; }
            else {
                int v = g_objth[row];
                if (v >= 0) { m = v; lab = s_glab[m]; }
                else        { m = 0; lab = 0; }
            }
            const float* cp = sw + lane * C;          // stride 21 words: conflict-free
            float mx = cp[0];
            for (int c = 1; c < C; c++) mx = fmaxf(mx, cp[c]);
            float s = 0.f;
            for (int c = 0; c < C; c++) s += __expf(cp[c] - mx);
            float ce = __logf(s) - (cp[lab] - mx);

            if (lab > 0) {
                npos++; conf += ce; g_ce[row] = 0.f;
                float4 g = s_g[m];
                float gcx = (g.x + g.z) * 0.5f, gcy = (g.y + g.w) * 0.5f;
                float gw = g.z - g.x, gh = g.w - g.y;
                float4 pb = db4[r];
                float e0 = (gcx - pb.x) * 10.0f / pb.z;
                float e1 = (gcy - pb.y) * 10.0f / pb.w;
                float e2 = __logf(gw / pb.z) * 5.0f;
                float e3 = __logf(gh / pb.w) * 5.0f;
                float4 lp = ((const float4*)loc_pred)[row];
                float dd2, ad;
                dd2 = lp.x - e0; ad = fabsf(dd2); locs += (ad < 1.f) ? 0.5f*dd2*dd2 : ad - 0.5f;
                dd2 = lp.y - e1; ad = fabsf(dd2); locs += (ad < 1.f) ? 0.5f*dd2*dd2 : ad - 0.5f;
                dd2 = lp.z - e2; ad = fabsf(dd2); locs += (ad < 1.f) ? 0.5f*dd2*dd2 : ad - 0.5f;
                dd2 = lp.w - e3; ad = fabsf(dd2); locs += (ad < 1.f) ? 0.5f*dd2*dd2 : ad - 0.5f;
            } else {
                g_ce[row] = ce;
            }
        }
        __syncwarp();
    }
    __syncthreads();

    npos = blockReduceSumI(npos, s_redi);
    conf = blockReduceSumF(conf, s_redf);
    locs = blockReduceSumF(locs, s_redf);
    if (tid == 0) {
        int slot = b * gridDim.x + t;
        g_partc[slot] = conf;
        g_partl[slot] = locs;
        g_parti[slot] = npos;
    }
}

// ==== K3: per-batch radix-select mining + deterministic totals + finale =====
// 1 CTA/batch, 1024 threads. dyn smem: s_ce[D] f32.
__global__ void __launch_bounds__(1024, 1)
mb_mine_kernel(float* __restrict__ out, int D, int B, int ntile)
{
    extern __shared__ float s_ce[];
    __shared__ int   s_hist[1024];
    __shared__ int   s_suf[1024];
    __shared__ float s_redf[32];
    __shared__ int   s_redi[32];
    __shared__ int   s_bcast[2];
    __shared__ int   s_last;
    __shared__ float s_cl[2];
    __shared__ int   s_np;

    const int b = blockIdx.x;
    const int tid = threadIdx.x;
    const int T = blockDim.x;        // 1024

    if (tid == 0) {
        float c = 0.f, l = 0.f; int np = 0;
        for (int t = 0; t < ntile; t++) {              // fixed order: deterministic
            c  += g_partc[b * ntile + t];
            l  += g_partl[b * ntile + t];
            np += g_parti[b * ntile + t];
        }
        s_cl[0] = c; s_cl[1] = l; s_np = np;
    }
    for (int d = tid; d < D; d += T) s_ce[d] = g_ce[(size_t)b * D + d];
    __syncthreads();

    int n_pos = s_np;
    float conf_b = s_cl[0], loc_b = s_cl[1];

    float neg_sum = 0.f;
    int k = 3 * n_pos;
    if (k > D) k = D;
    if (k > 0) {
        unsigned prefix = 0;
        int above = 0;
#pragma unroll
        for (int pass = 0; pass < 3; pass++) {
            int shift = 21 - pass * 10;          // 21, 11, 1
            s_hist[tid] = 0;
            __syncthreads();
            for (int d = tid; d < D; d += T) {
                unsigned v = __float_as_uint(s_ce[d]);
                if ((v >> (shift + 10)) == prefix)
                    atomicAdd(&s_hist[(v >> shift) & 1023], 1);
            }
            __syncthreads();
            s_suf[tid] = s_hist[tid];
            __syncthreads();
            for (int st = 1; st < 1024; st <<= 1) {
                int add = (tid + st < 1024) ? s_suf[tid + st] : 0;
                __syncthreads();
                s_suf[tid] += add;
                __syncthreads();
            }
            int Si  = s_suf[tid];
            int Si1 = (tid < 1023) ? s_suf[tid + 1] : 0;
            if (above + Si >= k && above + Si1 < k) {
                s_bcast[0] = tid;
                s_bcast[1] = above + Si1;
            }
            __syncthreads();
            prefix = (prefix << 10) | (unsigned)s_bcast[0];
            above  = s_bcast[1];
            __syncthreads();
        }
        int c1 = 0;
        for (int d = tid; d < D; d += T) {
            unsigned v = __float_as_uint(s_ce[d]);
            if ((v >> 1) == prefix && (v & 1u)) c1++;
        }
        c1 = blockReduceSumI(c1, s_redi);
        unsigned thrbits = (above + c1 >= k) ? ((prefix << 1) | 1u) : (prefix << 1);
        float tf = __uint_as_float(thrbits);

        int cgt = 0; float sgt = 0.f;
        for (int d = tid; d < D; d += T) {
            float v = s_ce[d];
            if (v > tf) { cgt++; sgt += v; }
        }
        cgt = blockReduceSumI(cgt, s_redi);
        sgt = blockReduceSumF(sgt, s_redf);
        neg_sum = sgt + (float)(k - cgt) * tf;
    }

    if (tid == 0) {
        g_loss[b] = conf_b + neg_sum + loc_b;
        g_npos[b] = n_pos;
        __threadfence();
        int done = atomicAdd(&g_count, 1);
        s_last = (done == B - 1) ? 1 : 0;
    }
    __syncthreads();

    if (s_last) {
        __threadfence();
        float tsum = 0.f; int np = 0;
        for (int i = tid; i < B; i += T) {
            tsum += g_loss[i];
            np   += g_npos[i];
        }
        tsum = blockReduceSumF(tsum, s_redf);
        np   = blockReduceSumI(np, s_redi);
        if (tid == 0) {
            int nt = np > 0 ? np : 1;
            out[0] = tsum / (float)nt;
            g_count = 0;                 // reset for next replay
        }
    }
}

extern "C" void kernel_launch(void* const* d_in, const int* in_sizes, int n_in,
                              void* d_out, int out_size)
{
    const float* loc_pred = (const float*)d_in[0];
    const float* cls_pred = (const float*)d_in[1];
    const float* gt_boxes = (const float*)d_in[2];
    const int*   gt_labels= (const int*)  d_in[3];
    const float* dbox     = (const float*)d_in[4];

    int D = in_sizes[4] / 4;
    int B = in_sizes[0] / (D * 4);
    int C = (int)((long long)in_sizes[1] / ((long long)B * (long long)D));
    int M = in_sizes[2] / (B * 4);
    int nchunk = (D + K1_CHUNK - 1) / K1_CHUNK;

    // K1 (static smem only)
    dim3 g1(nchunk, B);
    mb_match_kernel<<<g1, K1_TPB>>>(gt_boxes, dbox, D, M);

    // K2
    size_t sm2 = (size_t)256 * C * 4;
    cudaFuncSetAttribute(mb_ce_kernel,
                         cudaFuncAttributeMaxDynamicSharedMemorySize, (int)sm2);
    dim3 g2(NTILE, B);
    mb_ce_kernel<<<g2, 256, sm2>>>(cls_pred, loc_pred, gt_boxes, gt_labels,
                                   dbox, D, M, C, nchunk);

    // K3
    size_t sm3 = (size_t)D * 4;
    cudaFuncSetAttribute(mb_mine_kernel,
                         cudaFuncAttributeMaxDynamicSharedMemorySize, (int)sm3);
    mb_mine_kernel<<<B, 1024, sm3>>>((float*)d_out, D, B, NTILE);
}

// round 16
// speedup vs baseline: 1.2420x; 1.2420x over previous
#include <cuda_runtime.h>

#define MAXROWS (1 << 22)
#define MAXB 2048
#define MAXM 32
#define NTILE 8
#define MAXDW 512     // force-bitmap words; supports D <= 16384
#define MAXCHUNK 16

#define K1_TPB 256
#define K1_ITER 4
#define K1_CHUNK (K1_TPB * K1_ITER)   // 1024 priors per CTA
#define K1_HALF (K1_TPB / 2)          // 128 key slots per m

__device__ short g_objth[MAXROWS];                       // -1 = below threshold, else obj idx
__device__ unsigned long long g_key[MAXB * MAXM * MAXCHUNK]; // per-(b,m,chunk) winner key
__device__ float g_ce[MAXROWS];
__device__ float g_partc[MAXB * NTILE];
__device__ float g_partl[MAXB * NTILE];
__device__ int   g_parti[MAXB * NTILE];
__device__ float g_loss[MAXB];
__device__ int   g_npos[MAXB];
__device__ int   g_count;                                // zero-init; self-reset

__device__ __forceinline__ float warpReduceSumF(float v) {
#pragma unroll
    for (int o = 16; o; o >>= 1) v += __shfl_down_sync(0xffffffffu, v, o);
    return v;
}
__device__ __forceinline__ int warpReduceSumI(int v) {
#pragma unroll
    for (int o = 16; o; o >>= 1) v += __shfl_down_sync(0xffffffffu, v, o);
    return v;
}
__device__ __forceinline__ float blockReduceSumF(float v, float* sh) {
    int lane = threadIdx.x & 31, wid = threadIdx.x >> 5;
    int nw = (blockDim.x + 31) >> 5;
    v = warpReduceSumF(v);
    if (lane == 0) sh[wid] = v;
    __syncthreads();
    float r = 0.f;
    if (wid == 0) {
        r = (lane < nw) ? sh[lane] : 0.f;
        r = warpReduceSumF(r);
        if (lane == 0) sh[0] = r;
    }
    __syncthreads();
    r = sh[0];
    __syncthreads();
    return r;
}
__device__ __forceinline__ int blockReduceSumI(int v, int* sh) {
    int lane = threadIdx.x & 31, wid = threadIdx.x >> 5;
    int nw = (blockDim.x + 31) >> 5;
    v = warpReduceSumI(v);
    if (lane == 0) sh[wid] = v;
    __syncthreads();
    int r = 0;
    if (wid == 0) {
        r = (lane < nw) ? sh[lane] : 0;
        r = warpReduceSumI(r);
        if (lane == 0) sh[0] = r;
    }
    __syncthreads();
    r = sh[0];
    __syncthreads();
    return r;
}

// ==== K1: R11 design + pair-merge (32KB key table, 4 CTA/SM). ================
// Reference-bit-identical IoU arithmetic; exact rational per-thread compares;
// quantized u64 keys above thread level (R11-proven semantics).
// grid (ceil(D/1024), B), 256 threads.
__global__ void __launch_bounds__(K1_TPB, 4)
mb_match_kernel(const float* __restrict__ gt_boxes,
                const float* __restrict__ dbox,
                int D, int M)
{
    __shared__ unsigned long long s_keys[MAXM * K1_HALF];   // 32 KB
    __shared__ float4 s_g[MAXM];
    __shared__ float  s_a[MAXM];
    __shared__ unsigned long long s_part[MAXM * 8];

    const int b = blockIdx.y;
    const int tid = threadIdx.x;
    const float4* db4 = (const float4*)dbox;

    if (tid < M) {
        float4 g = ((const float4*)gt_boxes)[(size_t)b * M + tid];  // xyxy
        s_g[tid] = g;
        s_a[tid] = (g.z - g.x) * (g.w - g.y);
    }
    __syncthreads();

    int   dd[K1_ITER];
    float px1[K1_ITER], py1[K1_ITER], px2[K1_ITER], py2[K1_ITER], pa[K1_ITER];
#pragma unroll
    for (int i = 0; i < K1_ITER; i++) {
        int d = blockIdx.x * K1_CHUNK + i * K1_TPB + tid;
        dd[i] = d;
        int dl = min(d, D - 1);         // phantoms mirror D-1: exact tie -> lose min-d
        float4 p = db4[dl];             // cxcywh
        px1[i] = p.x - p.z * 0.5f; py1[i] = p.y - p.w * 0.5f;
        px2[i] = p.x + p.z * 0.5f; py2[i] = p.y + p.w * 0.5f;
        pa[i]  = (px2[i] - px1[i]) * (py2[i] - py1[i]);   // reference area_b
    }

    float binter[K1_ITER], bden[K1_ITER];
    int   bi[K1_ITER];
#pragma unroll
    for (int i = 0; i < K1_ITER; i++) { binter[i] = -1.f; bden[i] = 1.f; bi[i] = 0; }

    for (int m = 0; m < M; m++) {
        float4 g = s_g[m];
        float ga = s_a[m];
        float minter = -1.f, mden = 1.f;
        int   md = dd[0];
#pragma unroll
        for (int i = 0; i < K1_ITER; i++) {
            // reference intersection (xyxy min/max, clip 0)
            float ww = fmaxf(fminf(g.z, px2[i]) - fmaxf(g.x, px1[i]), 0.f);
            float hh = fmaxf(fminf(g.w, py2[i]) - fmaxf(g.y, py1[i]), 0.f);
            float inter = ww * hh;
            float den = (ga + pa[i]) - inter;             // reference union
            // exact rational argmax (first-index tie-break)
            if (inter * bden[i] > binter[i] * den) { binter[i] = inter; bden[i] = den; bi[i] = m; }
            if (inter * mden > minter * den)       { minter = inter; mden = den; md = dd[i]; }
        }
        float iou = __fdividef(minter, mden);
        unsigned long long key =
            ((unsigned long long)__float_as_uint(iou) << 32)
            | (unsigned long long)(0xFFFFFFFFu - (unsigned)md);
        // pair-merge: even lanes absorb odd partner (u64 max = max-iou, min-d)
        unsigned long long oth = __shfl_down_sync(0xffffffffu, key, 1);
        if (oth > key) key = oth;
        if (!(tid & 1)) s_keys[m * K1_HALF + (tid >> 1)] = key;
    }

    // per-d labels: iou < 0.5  <=>  2*inter < den
#pragma unroll
    for (int i = 0; i < K1_ITER; i++)
        if (dd[i] < D)
            g_objth[(size_t)b * D + dd[i]] =
                (2.f * binter[i] < bden[i]) ? (short)-1 : (short)bi[i];
    __syncthreads();

    // per-m reduce: 8 threads/m over 128 entries, stride-8
    {
        int m = tid >> 3, s = tid & 7;
        if (m < M) {
            unsigned long long mx = 0ull;
            const unsigned long long* base = s_keys + (size_t)m * K1_HALF;
#pragma unroll
            for (int i = 0; i < K1_HALF / 8; i++) mx = max(mx, base[s + i * 8]);
            s_part[m * 8 + s] = mx;
        }
    }
    __syncthreads();
    if (tid < M) {
        unsigned long long mx = 0ull;
#pragma unroll
        for (int i = 0; i < 8; i++) mx = max(mx, s_part[tid * 8 + i]);
        g_key[((size_t)b * MAXM + tid) * MAXCHUNK + blockIdx.x] = mx;
    }
}

// ==== K2: CE + labels + loc, high occupancy. grid (NTILE, B), 256 threads ===
// dyn smem: 256*C floats staging.
__global__ void __launch_bounds__(256)
mb_ce_kernel(const float* __restrict__ cls_pred,
             const float* __restrict__ loc_pred,
             const float* __restrict__ gt_boxes,
             const int*   __restrict__ gt_labels,
             const float* __restrict__ dbox,
             int D, int M, int C, int nchunk)
{
    extern __shared__ float s_stage[];               // [8 warps][32*C]
    __shared__ float4 s_g[MAXM];
    __shared__ int    s_glab[MAXM];
    __shared__ int    s_dpg[MAXM];
    __shared__ unsigned s_fbit[MAXDW];
    __shared__ float  s_redf[32];
    __shared__ int    s_redi[32];

    const int b = blockIdx.y, t = blockIdx.x;
    const int tid = threadIdx.x;
    const int lane = tid & 31, w = tid >> 5;
    const int warps_per_batch = gridDim.x * 8;
    const int nwords = (D + 31) >> 5;
    const float4* db4 = (const float4*)dbox;

    for (int i = tid; i < nwords; i += 256) s_fbit[i] = 0u;
    if (tid < MAXM) s_dpg[tid] = -2;
    __syncthreads();
    if (tid < M) {
        float4 g = ((const float4*)gt_boxes)[(size_t)b * M + tid];
        s_g[tid] = g;
        s_glab[tid] = gt_labels[(size_t)b * M + tid];
        // u64-max reduce of per-chunk winner keys (deterministic)
        unsigned long long best = 0ull;
        for (int c = 0; c < nchunk; c++) {
            unsigned long long kk = g_key[((size_t)b * MAXM + tid) * MAXCHUNK + c];
            if (kk > best) best = kk;
        }
        int fd = (int)(0xFFFFFFFFu - (unsigned)(best & 0xFFFFFFFFull));
        s_dpg[tid] = fd;
        atomicOr(&s_fbit[fd >> 5], 1u << (fd & 31));
    }
    __syncthreads();

    float conf = 0.f, locs = 0.f;
    int npos = 0;
    int ntiles = (D + 31) >> 5;
    float* sw = s_stage + (size_t)w * 32 * C;

    for (int tt = t * 8 + w; tt < ntiles; tt += warps_per_batch) {
        int r0 = tt * 32;
        int nr = min(32, D - r0);
        const float* src = cls_pred + ((size_t)b * D + r0) * C;
        if (nr == 32) {
            const float4* s4 = (const float4*)src;
            int nf4 = 8 * C;
            for (int i = lane; i < nf4; i += 32)
                ((float4*)sw)[i] = s4[i];
        } else {
            int nf = nr * C;
            for (int i = lane; i < nf; i += 32)
                sw[i] = src[i];
        }
        __syncwarp();
        if (lane < nr) {
            int r = r0 + lane;
            size_t row = (size_t)b * D + r;
            // forced? (rare: bitmap test first, then last-write-wins scan)
            int mf = -1;
            if ((s_fbit[r >> 5] >> (r & 31)) & 1u) {
#pragma unroll
                for (int j = 0; j < MAXM; j++)
                    if (s_dpg[j] == r) mf = j;        // later j wins
            }
            int m, lab;
            if (mf >= 0) { m = mf; lab = s_glab[m]; }
            else {
                int v = g_objth[row];
                if (v >= 0) { m = v; lab = s_glab[m]; }
                else        { m = 0; lab = 0; }
            }
            const float* cp = sw + lane * C;          // stride 21 words: conflict-free
            float mx = cp[0];
            for (int c = 1; c < C; c++) mx = fmaxf(mx, cp[c]);
            float s = 0.f;
            for (int c = 0; c < C; c++) s += __expf(cp[c] - mx);
            float ce = __logf(s) - (cp[lab] - mx);

            if (lab > 0) {
                npos++; conf += ce; g_ce[row] = 0.f;
                float4 g = s_g[m];
                float gcx = (g.x + g.z) * 0.5f, gcy = (g.y + g.w) * 0.5f;
                float gw = g.z - g.x, gh = g.w - g.y;
                float4 pb = db4[r];
                float e0 = (gcx - pb.x) * 10.0f / pb.z;
                float e1 = (gcy - pb.y) * 10.0f / pb.w;
                float e2 = __logf(gw / pb.z) * 5.0f;
                float e3 = __logf(gh / pb.w) * 5.0f;
                float4 lp = ((const float4*)loc_pred)[row];
                float dd2, ad;
                dd2 = lp.x - e0; ad = fabsf(dd2); locs += (ad < 1.f) ? 0.5f*dd2*dd2 : ad - 0.5f;
                dd2 = lp.y - e1; ad = fabsf(dd2); locs += (ad < 1.f) ? 0.5f*dd2*dd2 : ad - 0.5f;
                dd2 = lp.z - e2; ad = fabsf(dd2); locs += (ad < 1.f) ? 0.5f*dd2*dd2 : ad - 0.5f;
                dd2 = lp.w - e3; ad = fabsf(dd2); locs += (ad < 1.f) ? 0.5f*dd2*dd2 : ad - 0.5f;
            } else {
                g_ce[row] = ce;
            }
        }
        __syncwarp();
    }
    __syncthreads();

    npos = blockReduceSumI(npos, s_redi);
    conf = blockReduceSumF(conf, s_redf);
    locs = blockReduceSumF(locs, s_redf);
    if (tid == 0) {
        int slot = b * gridDim.x + t;
        g_partc[slot] = conf;
        g_partl[slot] = locs;
        g_parti[slot] = npos;
    }
}

// ==== K3: radix-select mining, warp-shuffle suffix scan (2 syncs/pass) ======
// 1 CTA/batch, 1024 threads. dyn smem: s_ce[D] f32.
__global__ void __launch_bounds__(1024, 1)
mb_mine_kernel(float* __restrict__ out, int D, int B, int ntile)
{
    extern __shared__ float s_ce[];
    __shared__ int   s_hist[1024];
    __shared__ int   s_wsum[32];
    __shared__ float s_redf[32];
    __shared__ int   s_redi[32];
    __shared__ int   s_bcast[2];
    __shared__ int   s_last;
    __shared__ float s_cl[2];
    __shared__ int   s_np;

    const int b = blockIdx.x;
    const int tid = threadIdx.x;
    const int T = blockDim.x;        // 1024
    const int lane = tid & 31, w = tid >> 5;

    if (tid == 0) {
        float c = 0.f, l = 0.f; int np = 0;
        for (int t = 0; t < ntile; t++) {              // fixed order: deterministic
            c  += g_partc[b * ntile + t];
            l  += g_partl[b * ntile + t];
            np += g_parti[b * ntile + t];
        }
        s_cl[0] = c; s_cl[1] = l; s_np = np;
    }
    for (int d = tid; d < D; d += T) s_ce[d] = g_ce[(size_t)b * D + d];
    __syncthreads();

    int n_pos = s_np;
    float conf_b = s_cl[0], loc_b = s_cl[1];

    float neg_sum = 0.f;
    int k = 3 * n_pos;
    if (k > D) k = D;
    if (k > 0) {
        unsigned prefix = 0;
        int above = 0;
#pragma unroll
        for (int pass = 0; pass < 3; pass++) {
            int shift = 21 - pass * 10;          // 21, 11, 1
            s_hist[tid] = 0;
            __syncthreads();
            for (int d = tid; d < D; d += T) {
                unsigned v = __float_as_uint(s_ce[d]);
                if ((v >> (shift + 10)) == prefix)
                    atomicAdd(&s_hist[(v >> shift) & 1023], 1);
            }
            __syncthreads();
            // hierarchical suffix scan of s_hist[1024] (2 syncs)
            int h0 = s_hist[tid];
            int h = h0;
#pragma unroll
            for (int off = 1; off < 32; off <<= 1) {
                int o = __shfl_down_sync(0xffffffffu, h, off);
                if (lane + off < 32) h += o;
            }
            if (lane == 0) s_wsum[w] = h;        // warp total
            __syncthreads();
            if (w == 0) {
                int t0 = s_wsum[lane];
                int ts = t0;
#pragma unroll
                for (int off = 1; off < 32; off <<= 1) {
                    int o = __shfl_down_sync(0xffffffffu, ts, off);
                    if (lane + off < 32) ts += o;
                }
                s_wsum[lane] = ts - t0;          // exclusive suffix of later warps
            }
            __syncthreads();
            int Si  = h + s_wsum[w];             // suffix sum from bin tid
            int Si1 = Si - h0;                   // suffix sum from bin tid+1
            if (above + Si >= k && above + Si1 < k) {
                s_bcast[0] = tid;
                s_bcast[1] = above + Si1;
            }
            __syncthreads();
            prefix = (prefix << 10) | (unsigned)s_bcast[0];
            above  = s_bcast[1];
        }
        int c1 = 0;
        for (int d = tid; d < D; d += T) {
            unsigned v = __float_as_uint(s_ce[d]);
            if ((v >> 1) == prefix && (v & 1u)) c1++;
        }
        c1 = blockReduceSumI(c1, s_redi);
        unsigned thrbits = (above + c1 >= k) ? ((prefix << 1) | 1u) : (prefix << 1);
        float tf = __uint_as_float(thrbits);

        int cgt = 0; float sgt = 0.f;
        for (int d = tid; d < D; d += T) {
            float v = s_ce[d];
            if (v > tf) { cgt++; sgt += v; }
        }
        cgt = blockReduceSumI(cgt, s_redi);
        sgt = blockReduceSumF(sgt, s_redf);
        neg_sum = sgt + (float)(k - cgt) * tf;
    }

    if (tid == 0) {
        g_loss[b] = conf_b + neg_sum + loc_b;
        g_npos[b] = n_pos;
        __threadfence();
        int done = atomicAdd(&g_count, 1);
        s_last = (done == B - 1) ? 1 : 0;
    }
    __syncthreads();

    if (s_last) {
        __threadfence();
        float tsum = 0.f; int np = 0;
        for (int i = tid; i < B; i += T) {
            tsum += g_loss[i];
            np   += g_npos[i];
        }
        tsum = blockReduceSumF(tsum, s_redf);
        np   = blockReduceSumI(np, s_redi);
        if (tid == 0) {
            int nt = np > 0 ? np : 1;
            out[0] = tsum / (float)nt;
            g_count = 0;                 // reset for next replay
        }
    }
}

extern "C" void kernel_launch(void* const* d_in, const int* in_sizes, int n_in,
                              void* d_out, int out_size)
{
    const float* loc_pred = (const float*)d_in[0];
    const float* cls_pred = (const float*)d_in[1];
    const float* gt_boxes = (const float*)d_in[2];
    const int*   gt_labels= (const int*)  d_in[3];
    const float* dbox     = (const float*)d_in[4];

    int D = in_sizes[4] / 4;
    int B = in_sizes[0] / (D * 4);
    int C = (int)((long long)in_sizes[1] / ((long long)B * (long long)D));
    int M = in_sizes[2] / (B * 4);
    int nchunk = (D + K1_CHUNK - 1) / K1_CHUNK;

    // K1 (static smem only, ~35KB)
    dim3 g1(nchunk, B);
    mb_match_kernel<<<g1, K1_TPB>>>(gt_boxes, dbox, D, M);

    // K2
    size_t sm2 = (size_t)256 * C * 4;
    cudaFuncSetAttribute(mb_ce_kernel,
                         cudaFuncAttributeMaxDynamicSharedMemorySize, (int)sm2);
    dim3 g2(NTILE, B);
    mb_ce_kernel<<<g2, 256, sm2>>>(cls_pred, loc_pred, gt_boxes, gt_labels,
                                   dbox, D, M, C, nchunk);

    // K3
    size_t sm3 = (size_t)D * 4;
    cudaFuncSetAttribute(mb_mine_kernel,
                         cudaFuncAttributeMaxDynamicSharedMemorySize, (int)sm3);
    mb_mine_kernel<<<B, 1024, sm3>>>((float*)d_out, D, B, NTILE);
}

// round 17
// speedup vs baseline: 1.2626x; 1.0166x over previous
#include <cuda_runtime.h>

#define MAXROWS (1 << 22)
#define MAXB 2048
#define MAXM 32
#define NTILE 16
#define MAXDW 512     // force-bitmap words; supports D <= 16384
#define MAXCHUNK 16

#define K1_TPB 256
#define K1_ITER 4
#define K1_CHUNK (K1_TPB * K1_ITER)   // 1024 priors per CTA
#define K1_HALF (K1_TPB / 2)          // 128 key slots per m

__device__ short g_objth[MAXROWS];                       // -1 = below threshold, else obj idx
__device__ unsigned long long g_key[MAXB * MAXM * MAXCHUNK]; // per-(b,m,chunk) winner key
__device__ float g_ce[MAXROWS];
__device__ float g_partc[MAXB * NTILE];
__device__ float g_partl[MAXB * NTILE];
__device__ int   g_parti[MAXB * NTILE];
__device__ float g_loss[MAXB];
__device__ int   g_npos[MAXB];
__device__ int   g_count;                                // zero-init; self-reset

__device__ __forceinline__ float warpReduceSumF(float v) {
#pragma unroll
    for (int o = 16; o; o >>= 1) v += __shfl_down_sync(0xffffffffu, v, o);
    return v;
}
__device__ __forceinline__ int warpReduceSumI(int v) {
#pragma unroll
    for (int o = 16; o; o >>= 1) v += __shfl_down_sync(0xffffffffu, v, o);
    return v;
}
__device__ __forceinline__ float blockReduceSumF(float v, float* sh) {
    int lane = threadIdx.x & 31, wid = threadIdx.x >> 5;
    int nw = (blockDim.x + 31) >> 5;
    v = warpReduceSumF(v);
    if (lane == 0) sh[wid] = v;
    __syncthreads();
    float r = 0.f;
    if (wid == 0) {
        r = (lane < nw) ? sh[lane] : 0.f;
        r = warpReduceSumF(r);
        if (lane == 0) sh[0] = r;
    }
    __syncthreads();
    r = sh[0];
    __syncthreads();
    return r;
}
__device__ __forceinline__ int blockReduceSumI(int v, int* sh) {
    int lane = threadIdx.x & 31, wid = threadIdx.x >> 5;
    int nw = (blockDim.x + 31) >> 5;
    v = warpReduceSumI(v);
    if (lane == 0) sh[wid] = v;
    __syncthreads();
    int r = 0;
    if (wid == 0) {
        r = (lane < nw) ? sh[lane] : 0;
        r = warpReduceSumI(r);
        if (lane == 0) sh[0] = r;
    }
    __syncthreads();
    r = sh[0];
    __syncthreads();
    return r;
}

// ==== K1: IoUs once, ITER=4 priors/thread, per-pair fdividef + float argmax
// (R8-proven quantized semantics). Pair-merge -> 32KB key table -> u64 chunk
// winners. grid (ceil(D/1024), B), 256 threads.
__global__ void __launch_bounds__(K1_TPB, 4)
mb_match_kernel(const float* __restrict__ gt_boxes,
                const float* __restrict__ dbox,
                int D, int M)
{
    __shared__ unsigned long long s_keys[MAXM * K1_HALF];   // 32 KB
    __shared__ float4 s_g[MAXM];
    __shared__ float  s_a[MAXM];
    __shared__ unsigned long long s_part[MAXM * 8];

    const int b = blockIdx.y;
    const int tid = threadIdx.x;
    const float4* db4 = (const float4*)dbox;

    if (tid < M) {
        float4 g = ((const float4*)gt_boxes)[(size_t)b * M + tid];  // xyxy
        s_g[tid] = g;
        s_a[tid] = (g.z - g.x) * (g.w - g.y);
    }
    __syncthreads();

    const int dbase = blockIdx.x * K1_CHUNK + tid;

    float px1[K1_ITER], py1[K1_ITER], px2[K1_ITER], py2[K1_ITER], pa[K1_ITER];
#pragma unroll
    for (int i = 0; i < K1_ITER; i++) {
        int d = dbase + i * K1_TPB;
        int dl = min(d, D - 1);         // phantoms mirror D-1: equal iou -> lose min-d
        float4 p = db4[dl];             // cxcywh
        px1[i] = p.x - p.z * 0.5f; py1[i] = p.y - p.w * 0.5f;
        px2[i] = p.x + p.z * 0.5f; py2[i] = p.y + p.w * 0.5f;
        pa[i]  = (px2[i] - px1[i]) * (py2[i] - py1[i]);   // reference area_b
    }

    float biou[K1_ITER];
    int   bi[K1_ITER];
#pragma unroll
    for (int i = 0; i < K1_ITER; i++) { biou[i] = -1.f; bi[i] = 0; }

    for (int m = 0; m < M; m++) {
        float4 g = s_g[m];
        float ga = s_a[m];
        float miou = -1.f;
        int   md = dbase;
#pragma unroll
        for (int i = 0; i < K1_ITER; i++) {
            // reference intersection (xyxy min/max, clip 0)
            float ww = fmaxf(fminf(g.z, px2[i]) - fmaxf(g.x, px1[i]), 0.f);
            float hh = fmaxf(fminf(g.w, py2[i]) - fmaxf(g.y, py1[i]), 0.f);
            float inter = ww * hh;
            float den = (ga + pa[i]) - inter;             // reference union
            float iou = __fdividef(inter, den);
            // strict > : first-index tie-break in both reductions
            if (iou > biou[i]) { biou[i] = iou; bi[i] = m; }
            if (iou > miou)    { miou = iou; md = dbase + i * K1_TPB; }
        }
        unsigned long long key =
            ((unsigned long long)__float_as_uint(miou) << 32)
            | (unsigned long long)(0xFFFFFFFFu - (unsigned)md);
        // pair-merge: even lanes absorb odd partner (u64 max = max-iou, min-d)
        unsigned long long oth = __shfl_down_sync(0xffffffffu, key, 1);
        if (oth > key) key = oth;
        if (!(tid & 1)) s_keys[m * K1_HALF + (tid >> 1)] = key;
    }

    // per-d labels (R8 quantized form: iou < 0.5)
#pragma unroll
    for (int i = 0; i < K1_ITER; i++) {
        int d = dbase + i * K1_TPB;
        if (d < D)
            g_objth[(size_t)b * D + d] =
                (biou[i] < 0.5f) ? (short)-1 : (short)bi[i];
    }
    __syncthreads();

    // per-m reduce: 8 threads/m over 128 entries, stride-8
    {
        int m = tid >> 3, s = tid & 7;
        if (m < M) {
            unsigned long long mx = 0ull;
            const unsigned long long* base = s_keys + (size_t)m * K1_HALF;
#pragma unroll
            for (int i = 0; i < K1_HALF / 8; i++) mx = max(mx, base[s + i * 8]);
            s_part[m * 8 + s] = mx;
        }
    }
    __syncthreads();
    if (tid < M) {
        unsigned long long mx = 0ull;
#pragma unroll
        for (int i = 0; i < 8; i++) mx = max(mx, s_part[tid * 8 + i]);
        g_key[((size_t)b * MAXM + tid) * MAXCHUNK + blockIdx.x] = mx;
    }
}

// ==== K2: CE + labels + loc, high occupancy. grid (NTILE, B), 256 threads ===
// dyn smem: 256*C floats staging.
__global__ void __launch_bounds__(256)
mb_ce_kernel(const float* __restrict__ cls_pred,
             const float* __restrict__ loc_pred,
             const float* __restrict__ gt_boxes,
             const int*   __restrict__ gt_labels,
             const float* __restrict__ dbox,
             int D, int M, int C, int nchunk)
{
    extern __shared__ float s_stage[];               // [8 warps][32*C]
    __shared__ float4 s_g[MAXM];
    __shared__ int    s_glab[MAXM];
    __shared__ int    s_dpg[MAXM];
    __shared__ unsigned s_fbit[MAXDW];
    __shared__ float  s_redf[32];
    __shared__ int    s_redi[32];

    const int b = blockIdx.y, t = blockIdx.x;
    const int tid = threadIdx.x;
    const int lane = tid & 31, w = tid >> 5;
    const int warps_per_batch = gridDim.x * 8;
    const int nwords = (D + 31) >> 5;
    const float4* db4 = (const float4*)dbox;

    for (int i = tid; i < nwords; i += 256) s_fbit[i] = 0u;
    if (tid < MAXM) s_dpg[tid] = -2;
    __syncthreads();
    if (tid < M) {
        float4 g = ((const float4*)gt_boxes)[(size_t)b * M + tid];
        s_g[tid] = g;
        s_glab[tid] = gt_labels[(size_t)b * M + tid];
        // u64-max reduce of per-chunk winner keys (deterministic)
        unsigned long long best = 0ull;
        for (int c = 0; c < nchunk; c++) {
            unsigned long long kk = g_key[((size_t)b * MAXM + tid) * MAXCHUNK + c];
            if (kk > best) best = kk;
        }
        int fd = (int)(0xFFFFFFFFu - (unsigned)(best & 0xFFFFFFFFull));
        s_dpg[tid] = fd;
        atomicOr(&s_fbit[fd >> 5], 1u << (fd & 31));
    }
    __syncthreads();

    float conf = 0.f, locs = 0.f;
    int npos = 0;
    int ntiles = (D + 31) >> 5;
    float* sw = s_stage + (size_t)w * 32 * C;

    for (int tt = t * 8 + w; tt < ntiles; tt += warps_per_batch) {
        int r0 = tt * 32;
        int nr = min(32, D - r0);
        const float* src = cls_pred + ((size_t)b * D + r0) * C;
        if (nr == 32) {
            const float4* s4 = (const float4*)src;
            int nf4 = 8 * C;
            for (int i = lane; i < nf4; i += 32)
                ((float4*)sw)[i] = s4[i];
        } else {
            int nf = nr * C;
            for (int i = lane; i < nf; i += 32)
                sw[i] = src[i];
        }
        __syncwarp();
        if (lane < nr) {
            int r = r0 + lane;
            size_t row = (size_t)b * D + r;
            // forced? (rare: bitmap test first, then last-write-wins scan)
            int mf = -1;
            if ((s_fbit[r >> 5] >> (r & 31)) & 1u) {
#pragma unroll
                for (int j = 0; j < MAXM; j++)
                    if (s_dpg[j] == r) mf = j;        // later j wins
            }
            int m, lab;
            if (mf >= 0) { m = mf; lab = s_glab[m]; }
            else {
                int v = g_objth[row];
                if (v >= 0) { m = v; lab = s_glab[m]; }
                else        { m = 0; lab = 0; }
            }
            const float* cp = sw + lane * C;          // stride 21 words: conflict-free
            float mx = cp[0];
            for (int c = 1; c < C; c++) mx = fmaxf(mx, cp[c]);
            float s = 0.f;
            for (int c = 0; c < C; c++) s += __expf(cp[c] - mx);
            float ce = __logf(s) - (cp[lab] - mx);

            if (lab > 0) {
                npos++; conf += ce; g_ce[row] = 0.f;
                float4 g = s_g[m];
                float gcx = (g.x + g.z) * 0.5f, gcy = (g.y + g.w) * 0.5f;
                float gw = g.z - g.x, gh = g.w - g.y;
                float4 pb = db4[r];
                float e0 = (gcx - pb.x) * 10.0f / pb.z;
                float e1 = (gcy - pb.y) * 10.0f / pb.w;
                float e2 = __logf(gw / pb.z) * 5.0f;
                float e3 = __logf(gh / pb.w) * 5.0f;
                float4 lp = ((const float4*)loc_pred)[row];
                float dd2, ad;
                dd2 = lp.x - e0; ad = fabsf(dd2); locs += (ad < 1.f) ? 0.5f*dd2*dd2 : ad - 0.5f;
                dd2 = lp.y - e1; ad = fabsf(dd2); locs += (ad < 1.f) ? 0.5f*dd2*dd2 : ad - 0.5f;
                dd2 = lp.z - e2; ad = fabsf(dd2); locs += (ad < 1.f) ? 0.5f*dd2*dd2 : ad - 0.5f;
                dd2 = lp.w - e3; ad = fabsf(dd2); locs += (ad < 1.f) ? 0.5f*dd2*dd2 : ad - 0.5f;
            } else {
                g_ce[row] = ce;
            }
        }
        __syncwarp();
    }
    __syncthreads();

    npos = blockReduceSumI(npos, s_redi);
    conf = blockReduceSumF(conf, s_redf);
    locs = blockReduceSumF(locs, s_redf);
    if (tid == 0) {
        int slot = b * gridDim.x + t;
        g_partc[slot] = conf;
        g_partl[slot] = locs;
        g_parti[slot] = npos;
    }
}

// ==== K3: radix-select mining, warp-shuffle suffix scan (2 syncs/pass) ======
// 1 CTA/batch, 1024 threads. dyn smem: s_ce[D] f32.
__global__ void __launch_bounds__(1024, 1)
mb_mine_kernel(float* __restrict__ out, int D, int B, int ntile)
{
    extern __shared__ float s_ce[];
    __shared__ int   s_hist[1024];
    __shared__ int   s_wsum[32];
    __shared__ float s_redf[32];
    __shared__ int   s_redi[32];
    __shared__ int   s_bcast[2];
    __shared__ int   s_last;
    __shared__ float s_cl[2];
    __shared__ int   s_np;

    const int b = blockIdx.x;
    const int tid = threadIdx.x;
    const int T = blockDim.x;        // 1024
    const int lane = tid & 31, w = tid >> 5;

    if (tid == 0) {
        float c = 0.f, l = 0.f; int np = 0;
        for (int t = 0; t < ntile; t++) {              // fixed order: deterministic
            c  += g_partc[b * ntile + t];
            l  += g_partl[b * ntile + t];
            np += g_parti[b * ntile + t];
        }
        s_cl[0] = c; s_cl[1] = l; s_np = np;
    }
    for (int d = tid; d < D; d += T) s_ce[d] = g_ce[(size_t)b * D + d];
    __syncthreads();

    int n_pos = s_np;
    float conf_b = s_cl[0], loc_b = s_cl[1];

    float neg_sum = 0.f;
    int k = 3 * n_pos;
    if (k > D) k = D;
    if (k > 0) {
        unsigned prefix = 0;
        int above = 0;
#pragma unroll
        for (int pass = 0; pass < 3; pass++) {
            int shift = 21 - pass * 10;          // 21, 11, 1
            s_hist[tid] = 0;
            __syncthreads();
            for (int d = tid; d < D; d += T) {
                unsigned v = __float_as_uint(s_ce[d]);
                if ((v >> (shift + 10)) == prefix)
                    atomicAdd(&s_hist[(v >> shift) & 1023], 1);
            }
            __syncthreads();
            // hierarchical suffix scan of s_hist[1024] (2 syncs)
            int h0 = s_hist[tid];
            int h = h0;
#pragma unroll
            for (int off = 1; off < 32; off <<= 1) {
                int o = __shfl_down_sync(0xffffffffu, h, off);
                if (lane + off < 32) h += o;
            }
            if (lane == 0) s_wsum[w] = h;        // warp total
            __syncthreads();
            if (w == 0) {
                int t0 = s_wsum[lane];
                int ts = t0;
#pragma unroll
                for (int off = 1; off < 32; off <<= 1) {
                    int o = __shfl_down_sync(0xffffffffu, ts, off);
                    if (lane + off < 32) ts += o;
                }
                s_wsum[lane] = ts - t0;          // exclusive suffix of later warps
            }
            __syncthreads();
            int Si  = h + s_wsum[w];             // suffix sum from bin tid
            int Si1 = Si - h0;                   // suffix sum from bin tid+1
            if (above + Si >= k && above + Si1 < k) {
                s_bcast[0] = tid;
                s_bcast[1] = above + Si1;
            }
            __syncthreads();
            prefix = (prefix << 10) | (unsigned)s_bcast[0];
            above  = s_bcast[1];
        }
        int c1 = 0;
        for (int d = tid; d < D; d += T) {
            unsigned v = __float_as_uint(s_ce[d]);
            if ((v >> 1) == prefix && (v & 1u)) c1++;
        }
        c1 = blockReduceSumI(c1, s_redi);
        unsigned thrbits = (above + c1 >= k) ? ((prefix << 1) | 1u) : (prefix << 1);
        float tf = __uint_as_float(thrbits);

        int cgt = 0; float sgt = 0.f;
        for (int d = tid; d < D; d += T) {
            float v = s_ce[d];
            if (v > tf) { cgt++; sgt += v; }
        }
        cgt = blockReduceSumI(cgt, s_redi);
        sgt = blockReduceSumF(sgt, s_redf);
        neg_sum = sgt + (float)(k - cgt) * tf;
    }

    if (tid == 0) {
        g_loss[b] = conf_b + neg_sum + loc_b;
        g_npos[b] = n_pos;
        __threadfence();
        int done = atomicAdd(&g_count, 1);
        s_last = (done == B - 1) ? 1 : 0;
    }
    __syncthreads();

    if (s_last) {
        __threadfence();
        float tsum = 0.f; int np = 0;
        for (int i = tid; i < B; i += T) {
            tsum += g_loss[i];
            np   += g_npos[i];
        }
        tsum = blockReduceSumF(tsum, s_redf);
        np   = blockReduceSumI(np, s_redi);
        if (tid == 0) {
            int nt = np > 0 ? np : 1;
            out[0] = tsum / (float)nt;
            g_count = 0;                 // reset for next replay
        }
    }
}

extern "C" void kernel_launch(void* const* d_in, const int* in_sizes, int n_in,
                              void* d_out, int out_size)
{
    const float* loc_pred = (const float*)d_in[0];
    const float* cls_pred = (const float*)d_in[1];
    const float* gt_boxes = (const float*)d_in[2];
    const int*   gt_labels= (const int*)  d_in[3];
    const float* dbox     = (const float*)d_in[4];

    int D = in_sizes[4] / 4;
    int B = in_sizes[0] / (D * 4);
    int C = (int)((long long)in_sizes[1] / ((long long)B * (long long)D));
    int M = in_sizes[2] / (B * 4);
    int nchunk = (D + K1_CHUNK - 1) / K1_CHUNK;

    // K1 (static smem only, ~35KB)
    dim3 g1(nchunk, B);
    mb_match_kernel<<<g1, K1_TPB>>>(gt_boxes, dbox, D, M);

    // K2
    size_t sm2 = (size_t)256 * C * 4;
    cudaFuncSetAttribute(mb_ce_kernel,
                         cudaFuncAttributeMaxDynamicSharedMemorySize, (int)sm2);
    dim3 g2(NTILE, B);
    mb_ce_kernel<<<g2, 256, sm2>>>(cls_pred, loc_pred, gt_boxes, gt_labels,
                                   dbox, D, M, C, nchunk);

    // K3
    size_t sm3 = (size_t)D * 4;
    cudaFuncSetAttribute(mb_mine_kernel,
                         cudaFuncAttributeMaxDynamicSharedMemorySize, (int)sm3);
    mb_mine_kernel<<<B, 1024, sm3>>>((float*)d_out, D, B, NTILE);
}